// round 4
// baseline (speedup 1.0000x reference)
#include <cuda_runtime.h>

#define Bsz 1024
#define Hsz 2048
#define Asz 18
#define Tsteps 25
#define LSZ (Bsz * Hsz)

// Persistent scratch state (no device allocation allowed).
__device__ float g_mem[5 * LSZ];   // membranes m1..m5
__device__ float g_cur1[LSZ];      // time-invariant layer-1 current
__device__ float g_sA[LSZ];        // spike ping-pong buffers
__device__ float g_sB[LSZ];
__device__ float g_acc[Bsz * Asz]; // accumulated Q

// ---------------------------------------------------------------------------
__global__ void init_kernel() {
    int stride = gridDim.x * blockDim.x;
    int i0 = blockIdx.x * blockDim.x + threadIdx.x;
    for (int k = i0; k < 5 * LSZ; k += stride) g_mem[k] = 0.0f;
    for (int k = i0; k < Bsz * Asz; k += stride) g_acc[k] = 0.0f;
}

// Layer-1 LIF: mem = fma(0.9, mem, cur1); spike; subtract-reset. Spikes -> sA.
__global__ void lif1_kernel() {
    int i = blockIdx.x * blockDim.x + threadIdx.x;
    float mv = g_mem[i];
    mv = fmaf(0.9f, mv, g_cur1[i]);          // FMA-contracted, matches XLA fusion
    float sp = (mv > 1.0f) ? 1.0f : 0.0f;
    g_mem[i] = mv - sp;
    g_sA[i] = sp;
}

// ---------------------------------------------------------------------------
// C[M,N] = A[M,K] @ W[N,K]^T + bias (fp32, per-element serial ascending-k FMA
// chain -- matches cuBLAS/Eigen/XLA accumulation microstructure), optionally
// fused with LIF update.
#define BM 128
#define BN 128
#define BK 16

__global__ __launch_bounds__(256) void gemm_lif_kernel(
    const float* __restrict__ Aext,
    const float* __restrict__ W,
    const float* __restrict__ bias,
    int K, int mode, int mem_layer, int in_sel, int out_sel)
{
    __shared__ float As[BK][BM];
    __shared__ float Ws[BK][BN];

    const float* A = (in_sel == 2) ? Aext : (in_sel ? (const float*)g_sB : (const float*)g_sA);

    const int tid = threadIdx.x;
    const int m0 = blockIdx.y * BM;
    const int n0 = blockIdx.x * BN;
    const int tx = tid & 15;   // 0..15 -> N direction
    const int ty = tid >> 4;   // 0..15 -> M direction

    float acc[8][8];
#pragma unroll
    for (int i = 0; i < 8; i++)
#pragma unroll
        for (int j = 0; j < 8; j++) acc[i][j] = 0.0f;

    for (int k0 = 0; k0 < K; k0 += BK) {
        // Load 128x16 A tile and 128x16 W tile (K-contiguous), store transposed.
#pragma unroll
        for (int r = 0; r < 2; r++) {
            int idx = tid + r * 256;       // 0..511
            int row = idx >> 2;            // 0..127
            int kq  = idx & 3;             // 0..3 (float4 within BK=16)
            float4 va = *reinterpret_cast<const float4*>(A + (size_t)(m0 + row) * K + k0 + kq * 4);
            As[kq * 4 + 0][row] = va.x;
            As[kq * 4 + 1][row] = va.y;
            As[kq * 4 + 2][row] = va.z;
            As[kq * 4 + 3][row] = va.w;
            float4 vw = *reinterpret_cast<const float4*>(W + (size_t)(n0 + row) * K + k0 + kq * 4);
            Ws[kq * 4 + 0][row] = vw.x;
            Ws[kq * 4 + 1][row] = vw.y;
            Ws[kq * 4 + 2][row] = vw.z;
            Ws[kq * 4 + 3][row] = vw.w;
        }
        __syncthreads();

#pragma unroll
        for (int kk = 0; kk < BK; kk++) {
            float a[8], b[8];
            float4 a0 = *reinterpret_cast<const float4*>(&As[kk][ty * 8]);
            float4 a1 = *reinterpret_cast<const float4*>(&As[kk][ty * 8 + 4]);
            float4 b0 = *reinterpret_cast<const float4*>(&Ws[kk][tx * 8]);
            float4 b1 = *reinterpret_cast<const float4*>(&Ws[kk][tx * 8 + 4]);
            a[0] = a0.x; a[1] = a0.y; a[2] = a0.z; a[3] = a0.w;
            a[4] = a1.x; a[5] = a1.y; a[6] = a1.z; a[7] = a1.w;
            b[0] = b0.x; b[1] = b0.y; b[2] = b0.z; b[3] = b0.w;
            b[4] = b1.x; b[5] = b1.y; b[6] = b1.z; b[7] = b1.w;
#pragma unroll
            for (int i = 0; i < 8; i++)
#pragma unroll
                for (int j = 0; j < 8; j++)
                    acc[i][j] = fmaf(a[i], b[j], acc[i][j]);   // serial ascending-k FMA
        }
        __syncthreads();
    }

    float* mem  = g_mem + (size_t)mem_layer * LSZ;
    float* sout = out_sel ? (float*)g_sB : (float*)g_sA;

#pragma unroll
    for (int i = 0; i < 8; i++) {
        int row = m0 + ty * 8 + i;
#pragma unroll
        for (int j = 0; j < 8; j++) {
            int col = n0 + tx * 8 + j;
            float c = acc[i][j] + bias[col];
            size_t o = (size_t)row * Hsz + col;
            if (mode == 0) {
                g_cur1[o] = c;
            } else {
                float mv = mem[o];
                mv = fmaf(0.9f, mv, c);                 // FMA-contracted LIF
                float sp = (mv > 1.0f) ? 1.0f : 0.0f;
                mem[o] = mv - sp;
                sout[o] = sp;
            }
        }
    }
}

// ---------------------------------------------------------------------------
// Dueling head: per batch row b (one block): v = s5.Wv + bv, a = s5.Wa^T + ba,
// q = v + a - max(a); acc += q. Reads spikes from g_sA.
__global__ __launch_bounds__(256) void head_kernel(
    const float* __restrict__ Wv, const float* __restrict__ bv,
    const float* __restrict__ Wa, const float* __restrict__ ba)
{
    __shared__ float srow[Hsz];
    __shared__ float outs[19];   // [0..17]=a, [18]=v
    const int b = blockIdx.x;
    const int tid = threadIdx.x;

    for (int k = tid; k < Hsz; k += 256) srow[k] = g_sA[(size_t)b * Hsz + k];
    __syncthreads();

    const int wid = tid >> 5;
    const int lane = tid & 31;
    for (int j = wid; j < 19; j += 8) {
        const float* wr = (j < 18) ? (Wa + (size_t)j * Hsz) : Wv;
        float p = 0.0f;
        for (int k = lane; k < Hsz; k += 32) p = fmaf(srow[k], wr[k], p);
#pragma unroll
        for (int off = 16; off > 0; off >>= 1) p += __shfl_xor_sync(0xffffffffu, p, off);
        if (lane == 0) outs[j] = p + ((j < 18) ? ba[j] : bv[0]);
    }
    __syncthreads();

    if (tid < Asz) {
        float mx = outs[0];
#pragma unroll
        for (int j = 1; j < Asz; j++) mx = fmaxf(mx, outs[j]);
        float q = outs[18] + outs[tid] - mx;
        g_acc[b * Asz + tid] += q;
    }
}

__global__ void finalize_kernel(float* __restrict__ out) {
    int i = blockIdx.x * blockDim.x + threadIdx.x;
    if (i < Bsz * Asz) out[i] = g_acc[i] / 25.0f;
}

// ---------------------------------------------------------------------------
extern "C" void kernel_launch(void* const* d_in, const int* in_sizes, int n_in,
                              void* d_out, int out_size) {
    (void)in_sizes; (void)n_in; (void)out_size;
    const float* x  = (const float*)d_in[0];
    const float* W1 = (const float*)d_in[1];
    const float* b1 = (const float*)d_in[2];
    const float* W2 = (const float*)d_in[3];
    const float* b2 = (const float*)d_in[4];
    const float* W3 = (const float*)d_in[5];
    const float* b3 = (const float*)d_in[6];
    const float* W4 = (const float*)d_in[7];
    const float* b4 = (const float*)d_in[8];
    const float* W5 = (const float*)d_in[9];
    const float* b5 = (const float*)d_in[10];
    const float* Wv = (const float*)d_in[11];
    const float* bv = (const float*)d_in[12];
    const float* Wa = (const float*)d_in[13];
    const float* ba = (const float*)d_in[14];

    init_kernel<<<512, 256>>>();

    dim3 gg(Hsz / BN, Bsz / BM);   // (16, 8) = 128 CTAs

    // cur1 = x @ W1^T + b1 (time-invariant, computed once)
    gemm_lif_kernel<<<gg, 256>>>(x, W1, b1, 1024, /*mode=*/0, /*mem_layer=*/0,
                                 /*in_sel=*/2, /*out_sel=*/0);

    for (int t = 0; t < Tsteps; t++) {
        lif1_kernel<<<LSZ / 256, 256>>>();                                    // -> sA
        gemm_lif_kernel<<<gg, 256>>>(nullptr, W2, b2, 2048, 1, 1, 0, 1);      // sA -> sB
        gemm_lif_kernel<<<gg, 256>>>(nullptr, W3, b3, 2048, 1, 2, 1, 0);      // sB -> sA
        gemm_lif_kernel<<<gg, 256>>>(nullptr, W4, b4, 2048, 1, 3, 0, 1);      // sA -> sB
        gemm_lif_kernel<<<gg, 256>>>(nullptr, W5, b5, 2048, 1, 4, 1, 0);      // sB -> sA
        head_kernel<<<Bsz, 256>>>(Wv, bv, Wa, ba);                            // reads sA
    }

    finalize_kernel<<<(Bsz * Asz + 255) / 256, 256>>>((float*)d_out);
}

// round 5
// speedup vs baseline: 1.1164x; 1.1164x over previous
#include <cuda_runtime.h>

#define Bsz 1024
#define Hsz 2048
#define Asz 18
#define Tsteps 25
#define LSZ (Bsz * Hsz)

// Persistent scratch state (no device allocation allowed).
__device__ float g_mem[5 * LSZ];   // membranes m1..m5
__device__ float g_cur1[LSZ];      // time-invariant layer-1 current
__device__ float g_sA[LSZ];        // spike ping-pong buffers
__device__ float g_sB[LSZ];
__device__ float g_acc[Bsz * Asz]; // accumulated Q

// ---- packed f32x2 helpers (Blackwell): two independent rn-fp32 FMAs per instr
__device__ __forceinline__ unsigned long long pack2(float lo, float hi) {
    unsigned long long r;
    asm("mov.b64 %0, {%1, %2};" : "=l"(r) : "f"(lo), "f"(hi));
    return r;
}
__device__ __forceinline__ void fma2(unsigned long long& d,
                                     unsigned long long a, unsigned long long b) {
    asm("fma.rn.f32x2 %0, %1, %2, %0;" : "+l"(d) : "l"(a), "l"(b));
}
__device__ __forceinline__ float2 unpack2(unsigned long long v) {
    float2 f;
    asm("mov.b64 {%0, %1}, %2;" : "=f"(f.x), "=f"(f.y) : "l"(v));
    return f;
}

// ---------------------------------------------------------------------------
__global__ void init_kernel() {
    int stride = gridDim.x * blockDim.x;
    int i0 = blockIdx.x * blockDim.x + threadIdx.x;
    for (int k = i0; k < 5 * LSZ; k += stride) g_mem[k] = 0.0f;
    for (int k = i0; k < Bsz * Asz; k += stride) g_acc[k] = 0.0f;
}

// Layer-1 LIF: mem = fma(0.9, mem, cur1); spike; subtract-reset. Spikes -> sA.
__global__ void lif1_kernel() {
    int i = blockIdx.x * blockDim.x + threadIdx.x;
    float mv = g_mem[i];
    mv = fmaf(0.9f, mv, g_cur1[i]);
    float sp = (mv > 1.0f) ? 1.0f : 0.0f;
    g_mem[i] = mv - sp;
    g_sA[i] = sp;
}

// ---------------------------------------------------------------------------
// C[M,N] = A[M,K] @ W[N,K]^T + bias (fp32, per-element serial ascending-k FMA
// chain, two adjacent-n chains packed into one fma.rn.f32x2), optionally fused
// with LIF update. Double-buffered smem, padded to dodge bank conflicts.
#define BM 128
#define BN 128
#define BK 16
#define PAD 4
#define LDW (BM + PAD)   // == BN + PAD

__global__ __launch_bounds__(256) void gemm_lif_kernel(
    const float* __restrict__ Aext,
    const float* __restrict__ W,
    const float* __restrict__ bias,
    int K, int mode, int mem_layer, int in_sel, int out_sel)
{
    __shared__ float As[2][BK][LDW];
    __shared__ float Ws[2][BK][LDW];

    const float* A = (in_sel == 2) ? Aext : (in_sel ? (const float*)g_sB : (const float*)g_sA);

    const int tid = threadIdx.x;
    const int m0 = blockIdx.y * BM;
    const int n0 = blockIdx.x * BN;
    const int tx = tid & 15;   // 0..15 -> N direction
    const int ty = tid >> 4;   // 0..15 -> M direction

    // Per-thread global-load coordinates (2 float4 per array).
    const int r0row = tid >> 1;                 // 0..127   (idx = tid)
    const int r0kq  = (tid & 1) * 0 + (tid & 3 & 3);        // recomputed below
    // Use same scheme as before: idx = tid + r*256, row = idx>>2, kq = idx&3.

    unsigned long long acc2[8][4];
#pragma unroll
    for (int i = 0; i < 8; i++)
#pragma unroll
        for (int j = 0; j < 4; j++) acc2[i][j] = 0ULL;

    // ---- stage-0 load
    {
#pragma unroll
        for (int r = 0; r < 2; r++) {
            int idx = tid + r * 256;
            int row = idx >> 2;
            int kq  = idx & 3;
            float4 va = *reinterpret_cast<const float4*>(A + (size_t)(m0 + row) * K + kq * 4);
            As[0][kq * 4 + 0][row] = va.x;
            As[0][kq * 4 + 1][row] = va.y;
            As[0][kq * 4 + 2][row] = va.z;
            As[0][kq * 4 + 3][row] = va.w;
            float4 vw = *reinterpret_cast<const float4*>(W + (size_t)(n0 + row) * K + kq * 4);
            Ws[0][kq * 4 + 0][row] = vw.x;
            Ws[0][kq * 4 + 1][row] = vw.y;
            Ws[0][kq * 4 + 2][row] = vw.z;
            Ws[0][kq * 4 + 3][row] = vw.w;
        }
    }
    __syncthreads();

    int s = 0;
    for (int k0 = 0; k0 < K; k0 += BK) {
        // ---- prefetch next tile into registers
        float4 pa[2], pw[2];
        const bool has_next = (k0 + BK) < K;
        if (has_next) {
#pragma unroll
            for (int r = 0; r < 2; r++) {
                int idx = tid + r * 256;
                int row = idx >> 2;
                int kq  = idx & 3;
                pa[r] = *reinterpret_cast<const float4*>(A + (size_t)(m0 + row) * K + (k0 + BK) + kq * 4);
                pw[r] = *reinterpret_cast<const float4*>(W + (size_t)(n0 + row) * K + (k0 + BK) + kq * 4);
            }
        }

        // ---- compute current stage
#pragma unroll
        for (int kk = 0; kk < BK; kk++) {
            float4 b0 = *reinterpret_cast<const float4*>(&Ws[s][kk][tx * 4]);
            float4 b1 = *reinterpret_cast<const float4*>(&Ws[s][kk][64 + tx * 4]);
            unsigned long long bp[4];
            bp[0] = pack2(b0.x, b0.y);
            bp[1] = pack2(b0.z, b0.w);
            bp[2] = pack2(b1.x, b1.y);
            bp[3] = pack2(b1.z, b1.w);

            float4 a0 = *reinterpret_cast<const float4*>(&As[s][kk][ty * 8]);
            float4 a1 = *reinterpret_cast<const float4*>(&As[s][kk][ty * 8 + 4]);
            unsigned long long ad[8];
            ad[0] = pack2(a0.x, a0.x);
            ad[1] = pack2(a0.y, a0.y);
            ad[2] = pack2(a0.z, a0.z);
            ad[3] = pack2(a0.w, a0.w);
            ad[4] = pack2(a1.x, a1.x);
            ad[5] = pack2(a1.y, a1.y);
            ad[6] = pack2(a1.z, a1.z);
            ad[7] = pack2(a1.w, a1.w);

#pragma unroll
            for (int i = 0; i < 8; i++)
#pragma unroll
                for (int j = 0; j < 4; j++)
                    fma2(acc2[i][j], ad[i], bp[j]);   // serial ascending-k, 2 chains/instr
        }

        // ---- drain prefetch into the other buffer
        if (has_next) {
#pragma unroll
            for (int r = 0; r < 2; r++) {
                int idx = tid + r * 256;
                int row = idx >> 2;
                int kq  = idx & 3;
                As[s ^ 1][kq * 4 + 0][row] = pa[r].x;
                As[s ^ 1][kq * 4 + 1][row] = pa[r].y;
                As[s ^ 1][kq * 4 + 2][row] = pa[r].z;
                As[s ^ 1][kq * 4 + 3][row] = pa[r].w;
                Ws[s ^ 1][kq * 4 + 0][row] = pw[r].x;
                Ws[s ^ 1][kq * 4 + 1][row] = pw[r].y;
                Ws[s ^ 1][kq * 4 + 2][row] = pw[r].z;
                Ws[s ^ 1][kq * 4 + 3][row] = pw[r].w;
            }
        }
        __syncthreads();
        s ^= 1;
    }

    // ---- epilogue: bias + (optional) LIF, vectorized over each 4-col group
    float* mem  = g_mem + (size_t)mem_layer * LSZ;
    float* sout = out_sel ? (float*)g_sB : (float*)g_sA;

#pragma unroll
    for (int i = 0; i < 8; i++) {
        int row = m0 + ty * 8 + i;
#pragma unroll
        for (int g = 0; g < 2; g++) {
            int cb = n0 + g * 64 + tx * 4;            // 4 consecutive cols
            float2 p0 = unpack2(acc2[i][g * 2 + 0]);
            float2 p1 = unpack2(acc2[i][g * 2 + 1]);
            float4 bz = *reinterpret_cast<const float4*>(bias + cb);
            float4 c;
            c.x = p0.x + bz.x;
            c.y = p0.y + bz.y;
            c.z = p1.x + bz.z;
            c.w = p1.y + bz.w;
            size_t o = (size_t)row * Hsz + cb;
            if (mode == 0) {
                *reinterpret_cast<float4*>(g_cur1 + o) = c;
            } else {
                float4 mv = *reinterpret_cast<const float4*>(mem + o);
                mv.x = fmaf(0.9f, mv.x, c.x);
                mv.y = fmaf(0.9f, mv.y, c.y);
                mv.z = fmaf(0.9f, mv.z, c.z);
                mv.w = fmaf(0.9f, mv.w, c.w);
                float4 sp;
                sp.x = (mv.x > 1.0f) ? 1.0f : 0.0f;
                sp.y = (mv.y > 1.0f) ? 1.0f : 0.0f;
                sp.z = (mv.z > 1.0f) ? 1.0f : 0.0f;
                sp.w = (mv.w > 1.0f) ? 1.0f : 0.0f;
                mv.x -= sp.x; mv.y -= sp.y; mv.z -= sp.z; mv.w -= sp.w;
                *reinterpret_cast<float4*>(mem + o) = mv;
                *reinterpret_cast<float4*>(sout + o) = sp;
            }
        }
    }
}

// ---------------------------------------------------------------------------
// Dueling head: per batch row b (one block): v = s5.Wv + bv, a = s5.Wa^T + ba,
// q = v + a - max(a); acc += q. Reads spikes from g_sA.
__global__ __launch_bounds__(256) void head_kernel(
    const float* __restrict__ Wv, const float* __restrict__ bv,
    const float* __restrict__ Wa, const float* __restrict__ ba)
{
    __shared__ float srow[Hsz];
    __shared__ float outs[19];   // [0..17]=a, [18]=v
    const int b = blockIdx.x;
    const int tid = threadIdx.x;

    for (int k = tid; k < Hsz; k += 256) srow[k] = g_sA[(size_t)b * Hsz + k];
    __syncthreads();

    const int wid = tid >> 5;
    const int lane = tid & 31;
    for (int j = wid; j < 19; j += 8) {
        const float* wr = (j < 18) ? (Wa + (size_t)j * Hsz) : Wv;
        float p = 0.0f;
        for (int k = lane; k < Hsz; k += 32) p = fmaf(srow[k], wr[k], p);
#pragma unroll
        for (int off = 16; off > 0; off >>= 1) p += __shfl_xor_sync(0xffffffffu, p, off);
        if (lane == 0) outs[j] = p + ((j < 18) ? ba[j] : bv[0]);
    }
    __syncthreads();

    if (tid < Asz) {
        float mx = outs[0];
#pragma unroll
        for (int j = 1; j < Asz; j++) mx = fmaxf(mx, outs[j]);
        float q = outs[18] + outs[tid] - mx;
        g_acc[b * Asz + tid] += q;
    }
}

__global__ void finalize_kernel(float* __restrict__ out) {
    int i = blockIdx.x * blockDim.x + threadIdx.x;
    if (i < Bsz * Asz) out[i] = g_acc[i] / 25.0f;
}

// ---------------------------------------------------------------------------
extern "C" void kernel_launch(void* const* d_in, const int* in_sizes, int n_in,
                              void* d_out, int out_size) {
    (void)in_sizes; (void)n_in; (void)out_size;
    const float* x  = (const float*)d_in[0];
    const float* W1 = (const float*)d_in[1];
    const float* b1 = (const float*)d_in[2];
    const float* W2 = (const float*)d_in[3];
    const float* b2 = (const float*)d_in[4];
    const float* W3 = (const float*)d_in[5];
    const float* b3 = (const float*)d_in[6];
    const float* W4 = (const float*)d_in[7];
    const float* b4 = (const float*)d_in[8];
    const float* W5 = (const float*)d_in[9];
    const float* b5 = (const float*)d_in[10];
    const float* Wv = (const float*)d_in[11];
    const float* bv = (const float*)d_in[12];
    const float* Wa = (const float*)d_in[13];
    const float* ba = (const float*)d_in[14];

    init_kernel<<<512, 256>>>();

    dim3 gg(Hsz / BN, Bsz / BM);   // (16, 8) = 128 CTAs

    // cur1 = x @ W1^T + b1 (time-invariant, computed once)
    gemm_lif_kernel<<<gg, 256>>>(x, W1, b1, 1024, /*mode=*/0, /*mem_layer=*/0,
                                 /*in_sel=*/2, /*out_sel=*/0);

    for (int t = 0; t < Tsteps; t++) {
        lif1_kernel<<<LSZ / 256, 256>>>();                                    // -> sA
        gemm_lif_kernel<<<gg, 256>>>(nullptr, W2, b2, 2048, 1, 1, 0, 1);      // sA -> sB
        gemm_lif_kernel<<<gg, 256>>>(nullptr, W3, b3, 2048, 1, 2, 1, 0);      // sB -> sA
        gemm_lif_kernel<<<gg, 256>>>(nullptr, W4, b4, 2048, 1, 3, 0, 1);      // sA -> sB
        gemm_lif_kernel<<<gg, 256>>>(nullptr, W5, b5, 2048, 1, 4, 1, 0);      // sB -> sA
        head_kernel<<<Bsz, 256>>>(Wv, bv, Wa, ba);                            // reads sA
    }

    finalize_kernel<<<(Bsz * Asz + 255) / 256, 256>>>((float*)d_out);
}

// round 6
// speedup vs baseline: 1.3962x; 1.2506x over previous
#include <cuda_runtime.h>

#define Bsz 1024
#define Hsz 2048
#define Asz 18
#define Tsteps 25
#define LSZ (Bsz * Hsz)

// Persistent scratch state (no device allocation allowed).
__device__ float g_mem[5 * LSZ];   // membranes m1..m5
__device__ float g_cur1[LSZ];      // time-invariant layer-1 current
__device__ float g_sA[LSZ];        // spike ping-pong buffers
__device__ float g_sB[LSZ];
__device__ float g_acc[Bsz * Asz]; // accumulated Q

typedef unsigned long long u64;

// ---- packed f32x2 helpers (Blackwell): two independent rn-fp32 FMAs per instr
__device__ __forceinline__ u64 pack2(float lo, float hi) {
    u64 r;
    asm("mov.b64 %0, {%1, %2};" : "=l"(r) : "f"(lo), "f"(hi));
    return r;
}
__device__ __forceinline__ void fma2(u64& d, u64 a, u64 b) {
    asm("fma.rn.f32x2 %0, %1, %2, %0;" : "+l"(d) : "l"(a), "l"(b));
}
__device__ __forceinline__ float2 unpack2(u64 v) {
    float2 f;
    asm("mov.b64 {%0, %1}, %2;" : "=f"(f.x), "=f"(f.y) : "l"(v));
    return f;
}

// ---------------------------------------------------------------------------
__global__ void init_kernel() {
    int stride = gridDim.x * blockDim.x;
    int i0 = blockIdx.x * blockDim.x + threadIdx.x;
    for (int k = i0; k < 5 * LSZ; k += stride) g_mem[k] = 0.0f;
    for (int k = i0; k < Bsz * Asz; k += stride) g_acc[k] = 0.0f;
}

// Layer-1 LIF: mem = fma(0.9, mem, cur1); spike; subtract-reset. Spikes -> sA.
__global__ void lif1_kernel() {
    int i = blockIdx.x * blockDim.x + threadIdx.x;
    float mv = g_mem[i];
    mv = fmaf(0.9f, mv, g_cur1[i]);
    float sp = (mv > 1.0f) ? 1.0f : 0.0f;
    g_mem[i] = mv - sp;
    g_sA[i] = sp;
}

// ---------------------------------------------------------------------------
// C[M,N] = A[M,K] @ W[N,K]^T + bias (fp32, per-element serial ascending-k FMA
// chain; two adjacent-M chains packed per fma.rn.f32x2 so packed A operands
// come straight out of shared memory), optionally fused with LIF update.
// 512 threads/CTA (16 warps/SM), double-buffered smem, conflict-free padding.
#define BM 128
#define BN 128
#define BK 16
#define LDW 136          // 128 + 8: kq store groups land on disjoint bank octets
#define NTHR 512

__global__ __launch_bounds__(NTHR, 1) void gemm_lif_kernel(
    const float* __restrict__ Aext,
    const float* __restrict__ W,
    const float* __restrict__ bias,
    int K, int mode, int mem_layer, int in_sel, int out_sel)
{
    __shared__ float As[2][BK][LDW];
    __shared__ float Ws[2][BK][LDW];

    const float* A = (in_sel == 2) ? Aext : (in_sel ? (const float*)g_sB : (const float*)g_sA);

    const int tid = threadIdx.x;
    const int m0 = blockIdx.y * BM;
    const int n0 = blockIdx.x * BN;
    const int tx = tid & 31;   // 0..31 -> N direction (4 cols each)
    const int ty = tid >> 5;   // 0..15 -> M direction (8 rows each)

    // Global-load coordinates: one float4 per array per thread per stage.
    const int grow = tid >> 2;   // 0..127
    const int gkq  = tid & 3;    // 0..3

    // acc2[mi][j]: lo = (row ty*8+2*mi,   col tx*4+j)
    //              hi = (row ty*8+2*mi+1, col tx*4+j)
    u64 acc2[4][4];
#pragma unroll
    for (int i = 0; i < 4; i++)
#pragma unroll
        for (int j = 0; j < 4; j++) acc2[i][j] = 0ULL;

    // ---- stage-0 load
    {
        float4 va = *reinterpret_cast<const float4*>(A + (size_t)(m0 + grow) * K + gkq * 4);
        As[0][gkq * 4 + 0][grow] = va.x;
        As[0][gkq * 4 + 1][grow] = va.y;
        As[0][gkq * 4 + 2][grow] = va.z;
        As[0][gkq * 4 + 3][grow] = va.w;
        float4 vw = *reinterpret_cast<const float4*>(W + (size_t)(n0 + grow) * K + gkq * 4);
        Ws[0][gkq * 4 + 0][grow] = vw.x;
        Ws[0][gkq * 4 + 1][grow] = vw.y;
        Ws[0][gkq * 4 + 2][grow] = vw.z;
        Ws[0][gkq * 4 + 3][grow] = vw.w;
    }
    __syncthreads();

    int s = 0;
    for (int k0 = 0; k0 < K; k0 += BK) {
        // ---- prefetch next tile into registers
        float4 pa, pw;
        const bool has_next = (k0 + BK) < K;
        if (has_next) {
            pa = *reinterpret_cast<const float4*>(A + (size_t)(m0 + grow) * K + (k0 + BK) + gkq * 4);
            pw = *reinterpret_cast<const float4*>(W + (size_t)(n0 + grow) * K + (k0 + BK) + gkq * 4);
        }

        // ---- compute current stage
#pragma unroll
        for (int kk = 0; kk < BK; kk++) {
            // Packed A operands directly from smem (adjacent-m pairs).
            const ulonglong2* pa2 = reinterpret_cast<const ulonglong2*>(&As[s][kk][ty * 8]);
            ulonglong2 aA = pa2[0];
            ulonglong2 aB = pa2[1];
            u64 ad[4] = {aA.x, aA.y, aB.x, aB.y};

            float4 b0 = *reinterpret_cast<const float4*>(&Ws[s][kk][tx * 4]);
            u64 bd[4];
            bd[0] = pack2(b0.x, b0.x);
            bd[1] = pack2(b0.y, b0.y);
            bd[2] = pack2(b0.z, b0.z);
            bd[3] = pack2(b0.w, b0.w);

#pragma unroll
            for (int i = 0; i < 4; i++)
#pragma unroll
                for (int j = 0; j < 4; j++)
                    fma2(acc2[i][j], ad[i], bd[j]);   // serial ascending-k, 2 m-chains/instr
        }

        // ---- drain prefetch into the other buffer
        if (has_next) {
            As[s ^ 1][gkq * 4 + 0][grow] = pa.x;
            As[s ^ 1][gkq * 4 + 1][grow] = pa.y;
            As[s ^ 1][gkq * 4 + 2][grow] = pa.z;
            As[s ^ 1][gkq * 4 + 3][grow] = pa.w;
            Ws[s ^ 1][gkq * 4 + 0][grow] = pw.x;
            Ws[s ^ 1][gkq * 4 + 1][grow] = pw.y;
            Ws[s ^ 1][gkq * 4 + 2][grow] = pw.z;
            Ws[s ^ 1][gkq * 4 + 3][grow] = pw.w;
        }
        __syncthreads();
        s ^= 1;
    }

    // ---- epilogue: bias + (optional) LIF, float4 per row over this thread's 4 cols
    float* mem  = g_mem + (size_t)mem_layer * LSZ;
    float* sout = out_sel ? (float*)g_sB : (float*)g_sA;

    const int cb = n0 + tx * 4;
    float4 bz = *reinterpret_cast<const float4*>(bias + cb);

#pragma unroll
    for (int mi = 0; mi < 4; mi++) {
        float2 v0 = unpack2(acc2[mi][0]);
        float2 v1 = unpack2(acc2[mi][1]);
        float2 v2 = unpack2(acc2[mi][2]);
        float2 v3 = unpack2(acc2[mi][3]);
#pragma unroll
        for (int half = 0; half < 2; half++) {
            int row = m0 + ty * 8 + 2 * mi + half;
            float4 c;
            c.x = (half ? v0.y : v0.x) + bz.x;
            c.y = (half ? v1.y : v1.x) + bz.y;
            c.z = (half ? v2.y : v2.x) + bz.z;
            c.w = (half ? v3.y : v3.x) + bz.w;
            size_t o = (size_t)row * Hsz + cb;
            if (mode == 0) {
                *reinterpret_cast<float4*>(g_cur1 + o) = c;
            } else {
                float4 mv = *reinterpret_cast<const float4*>(mem + o);
                mv.x = fmaf(0.9f, mv.x, c.x);
                mv.y = fmaf(0.9f, mv.y, c.y);
                mv.z = fmaf(0.9f, mv.z, c.z);
                mv.w = fmaf(0.9f, mv.w, c.w);
                float4 sp;
                sp.x = (mv.x > 1.0f) ? 1.0f : 0.0f;
                sp.y = (mv.y > 1.0f) ? 1.0f : 0.0f;
                sp.z = (mv.z > 1.0f) ? 1.0f : 0.0f;
                sp.w = (mv.w > 1.0f) ? 1.0f : 0.0f;
                mv.x -= sp.x; mv.y -= sp.y; mv.z -= sp.z; mv.w -= sp.w;
                *reinterpret_cast<float4*>(mem + o) = mv;
                *reinterpret_cast<float4*>(sout + o) = sp;
            }
        }
    }
}

// ---------------------------------------------------------------------------
// Dueling head: per batch row b (one block): v = s5.Wv + bv, a = s5.Wa^T + ba,
// q = v + a - max(a); acc += q. Reads spikes from g_sA.
__global__ __launch_bounds__(256) void head_kernel(
    const float* __restrict__ Wv, const float* __restrict__ bv,
    const float* __restrict__ Wa, const float* __restrict__ ba)
{
    __shared__ float srow[Hsz];
    __shared__ float outs[19];   // [0..17]=a, [18]=v
    const int b = blockIdx.x;
    const int tid = threadIdx.x;

    for (int k = tid; k < Hsz; k += 256) srow[k] = g_sA[(size_t)b * Hsz + k];
    __syncthreads();

    const int wid = tid >> 5;
    const int lane = tid & 31;
    for (int j = wid; j < 19; j += 8) {
        const float* wr = (j < 18) ? (Wa + (size_t)j * Hsz) : Wv;
        float p = 0.0f;
        for (int k = lane; k < Hsz; k += 32) p = fmaf(srow[k], wr[k], p);
#pragma unroll
        for (int off = 16; off > 0; off >>= 1) p += __shfl_xor_sync(0xffffffffu, p, off);
        if (lane == 0) outs[j] = p + ((j < 18) ? ba[j] : bv[0]);
    }
    __syncthreads();

    if (tid < Asz) {
        float mx = outs[0];
#pragma unroll
        for (int j = 1; j < Asz; j++) mx = fmaxf(mx, outs[j]);
        float q = outs[18] + outs[tid] - mx;
        g_acc[b * Asz + tid] += q;
    }
}

__global__ void finalize_kernel(float* __restrict__ out) {
    int i = blockIdx.x * blockDim.x + threadIdx.x;
    if (i < Bsz * Asz) out[i] = g_acc[i] / 25.0f;
}

// ---------------------------------------------------------------------------
extern "C" void kernel_launch(void* const* d_in, const int* in_sizes, int n_in,
                              void* d_out, int out_size) {
    (void)in_sizes; (void)n_in; (void)out_size;
    const float* x  = (const float*)d_in[0];
    const float* W1 = (const float*)d_in[1];
    const float* b1 = (const float*)d_in[2];
    const float* W2 = (const float*)d_in[3];
    const float* b2 = (const float*)d_in[4];
    const float* W3 = (const float*)d_in[5];
    const float* b3 = (const float*)d_in[6];
    const float* W4 = (const float*)d_in[7];
    const float* b4 = (const float*)d_in[8];
    const float* W5 = (const float*)d_in[9];
    const float* b5 = (const float*)d_in[10];
    const float* Wv = (const float*)d_in[11];
    const float* bv = (const float*)d_in[12];
    const float* Wa = (const float*)d_in[13];
    const float* ba = (const float*)d_in[14];

    init_kernel<<<512, 256>>>();

    dim3 gg(Hsz / BN, Bsz / BM);   // (16, 8) = 128 CTAs

    // cur1 = x @ W1^T + b1 (time-invariant, computed once)
    gemm_lif_kernel<<<gg, NTHR>>>(x, W1, b1, 1024, /*mode=*/0, /*mem_layer=*/0,
                                  /*in_sel=*/2, /*out_sel=*/0);

    for (int t = 0; t < Tsteps; t++) {
        lif1_kernel<<<LSZ / 256, 256>>>();                                    // -> sA
        gemm_lif_kernel<<<gg, NTHR>>>(nullptr, W2, b2, 2048, 1, 1, 0, 1);     // sA -> sB
        gemm_lif_kernel<<<gg, NTHR>>>(nullptr, W3, b3, 2048, 1, 2, 1, 0);     // sB -> sA
        gemm_lif_kernel<<<gg, NTHR>>>(nullptr, W4, b4, 2048, 1, 3, 0, 1);     // sA -> sB
        gemm_lif_kernel<<<gg, NTHR>>>(nullptr, W5, b5, 2048, 1, 4, 1, 0);     // sB -> sA
        head_kernel<<<Bsz, 256>>>(Wv, bv, Wa, ba);                            // reads sA
    }

    finalize_kernel<<<(Bsz * Asz + 255) / 256, 256>>>((float*)d_out);
}